// round 8
// baseline (speedup 1.0000x reference)
#include <cuda_runtime.h>

#define NB 8
#define NN 512
#define DD 256
#define DH 64
#define NROWS (NB*NN)   // 4096

#define QKV_BLOCKS 128
#define GRID_TOTAL 444           // 3 CTAs/SM * 148 SMs, single wave

// e passthrough: 16777216 float4 total; 32KB chunks stolen per-warp
#define CHUNK4    2048
#define NCHUNKS   8192

// smem: attention needs Qs 1024 + KsT 8192 + S 8192 + Mj 512 = 17920 floats.
// qkv phase needs xs 8192 floats. Shared (sequential phases).
#define SMEM_BYTES (17920 * 4)

__device__ float g_Q[NROWS*DH];
__device__ float g_K[NROWS*DH];
__device__ float g_V[NROWS*DH];
__device__ int   g_chunk;        // copy work-stealing counter
__device__ int   g_done;         // qkv completion counter
__device__ int   g_exit;         // exit counter (for replay reset)

// ---------------------------------------------------------------------------
__device__ __forceinline__ void attention_tile(
    float* sm, int tile, const int* __restrict__ mask, float* __restrict__ out)
{
    float* Qs  = sm;                  // 1024
    float* KsT = sm + 1024;           // 8192 (K: 64k x 128j / V: 128j x 64d)
    float* S   = sm + 9216;           // 8192
    float* Mj  = sm + 17408;          // 512

    const int t  = threadIdx.x;
    const int b  = tile >> 5;
    const int i0 = (tile & 31) * 16;

    for (int j = t; j < NN; j += 256) Mj[j] = (float)mask[b*NN + j];
    {
        const float4* q4 = reinterpret_cast<const float4*>(g_Q + (size_t)(b*NN + i0)*DH);
        reinterpret_cast<float4*>(Qs)[t] = q4[t];
    }
    __syncthreads();

    const int tx = t & 31;
    const int ty = t >> 5;
    float4* Qs4  = reinterpret_cast<float4*>(Qs);
    float4* KsT4 = reinterpret_cast<float4*>(KsT);
    float4* S4   = reinterpret_cast<float4*>(S);

    for (int jt = 0; jt < 4; jt++) {
        const int j0 = jt * 128;
        {
            const int j    = t & 127;
            const int half = t >> 7;
            const float4* K4 = reinterpret_cast<const float4*>(g_K) +
                               (size_t)(b*NN + j0 + j) * 16;
            #pragma unroll
            for (int i2 = 0; i2 < 8; i2++) {
                int k4 = half*8 + i2;
                float4 v = K4[k4];
                KsT[(k4*4+0)*128 + j] = v.x;
                KsT[(k4*4+1)*128 + j] = v.y;
                KsT[(k4*4+2)*128 + j] = v.z;
                KsT[(k4*4+3)*128 + j] = v.w;
            }
        }
        __syncthreads();

        float acc[2][4];
        #pragma unroll
        for (int c = 0; c < 2; c++)
            #pragma unroll
            for (int a = 0; a < 4; a++) acc[c][a] = 0.f;

        #pragma unroll 4
        for (int k4 = 0; k4 < 16; k4++) {
            float4 q0 = Qs4[ ty    *16 + k4];
            float4 q1 = Qs4[(ty+8)*16 + k4];
            #pragma unroll
            for (int kk = 0; kk < 4; kk++) {
                float4 kv = KsT4[(k4*4 + kk)*32 + tx];
                float qa = reinterpret_cast<const float*>(&q0)[kk];
                float qb = reinterpret_cast<const float*>(&q1)[kk];
                acc[0][0] = fmaf(qa, kv.x, acc[0][0]);
                acc[0][1] = fmaf(qa, kv.y, acc[0][1]);
                acc[0][2] = fmaf(qa, kv.z, acc[0][2]);
                acc[0][3] = fmaf(qa, kv.w, acc[0][3]);
                acc[1][0] = fmaf(qb, kv.x, acc[1][0]);
                acc[1][1] = fmaf(qb, kv.y, acc[1][1]);
                acc[1][2] = fmaf(qb, kv.z, acc[1][2]);
                acc[1][3] = fmaf(qb, kv.w, acc[1][3]);
            }
        }

        {
            const float mi0 = Mj[i0 + ty];
            const float mi1 = Mj[i0 + ty + 8];
            const int jb = j0 + tx*4;
            float4 s0, s1;
            s0.x = (mi0*Mj[jb+0] != 0.f) ? acc[0][0]*0.125f : -1.0e9f;
            s0.y = (mi0*Mj[jb+1] != 0.f) ? acc[0][1]*0.125f : -1.0e9f;
            s0.z = (mi0*Mj[jb+2] != 0.f) ? acc[0][2]*0.125f : -1.0e9f;
            s0.w = (mi0*Mj[jb+3] != 0.f) ? acc[0][3]*0.125f : -1.0e9f;
            s1.x = (mi1*Mj[jb+0] != 0.f) ? acc[1][0]*0.125f : -1.0e9f;
            s1.y = (mi1*Mj[jb+1] != 0.f) ? acc[1][1]*0.125f : -1.0e9f;
            s1.z = (mi1*Mj[jb+2] != 0.f) ? acc[1][2]*0.125f : -1.0e9f;
            s1.w = (mi1*Mj[jb+3] != 0.f) ? acc[1][3]*0.125f : -1.0e9f;
            S4[ ty    *128 + (jb>>2)] = s0;
            S4[(ty+8)*128 + (jb>>2)] = s1;
        }
        __syncthreads();
    }

    // softmax: warp per row pair
    {
        const int warp = t >> 5, lane = t & 31;
        #pragma unroll
        for (int rr = 0; rr < 2; rr++) {
            int row = warp*2 + rr;
            float vals[16];
            float mx = -3.4e38f;
            #pragma unroll
            for (int m = 0; m < 16; m++) {
                vals[m] = S[row*NN + lane + 32*m];
                mx = fmaxf(mx, vals[m]);
            }
            #pragma unroll
            for (int o = 16; o > 0; o >>= 1)
                mx = fmaxf(mx, __shfl_xor_sync(0xffffffffu, mx, o));
            float sum = 0.f;
            #pragma unroll
            for (int m = 0; m < 16; m++) { vals[m] = __expf(vals[m] - mx); sum += vals[m]; }
            #pragma unroll
            for (int o = 16; o > 0; o >>= 1)
                sum += __shfl_xor_sync(0xffffffffu, sum, o);
            float inv = 1.f / sum;
            #pragma unroll
            for (int m = 0; m < 16; m++) S[row*NN + lane + 32*m] = vals[m]*inv;
        }
    }
    __syncthreads();

    // out = P @ V, V staged through smem in 4 j-tiles
    {
        const int ty4 = t >> 4;
        const int tx4 = t & 15;
        float4 acc = {0.f, 0.f, 0.f, 0.f};
        float4* Vs4 = reinterpret_cast<float4*>(KsT);
        const float4* __restrict__ V4 =
            reinterpret_cast<const float4*>(g_V) + (size_t)b*NN*16;

        for (int jt = 0; jt < 4; jt++) {
            const int j0 = jt * 128;
            #pragma unroll
            for (int i2 = 0; i2 < 8; i2++) {
                int idx = t + i2*256;
                int row = idx >> 4, c4 = idx & 15;
                Vs4[row*16 + c4] = V4[(size_t)(j0 + row)*16 + c4];
            }
            __syncthreads();

            #pragma unroll 4
            for (int j4 = 0; j4 < 32; j4++) {
                float4 s  = S4[ty4*128 + jt*32 + j4];
                float4 v0 = Vs4[(j4*4+0)*16 + tx4];
                float4 v1 = Vs4[(j4*4+1)*16 + tx4];
                float4 v2 = Vs4[(j4*4+2)*16 + tx4];
                float4 v3 = Vs4[(j4*4+3)*16 + tx4];
                acc.x = fmaf(s.x, v0.x, acc.x); acc.y = fmaf(s.x, v0.y, acc.y);
                acc.z = fmaf(s.x, v0.z, acc.z); acc.w = fmaf(s.x, v0.w, acc.w);
                acc.x = fmaf(s.y, v1.x, acc.x); acc.y = fmaf(s.y, v1.y, acc.y);
                acc.z = fmaf(s.y, v1.z, acc.z); acc.w = fmaf(s.y, v1.w, acc.w);
                acc.x = fmaf(s.z, v2.x, acc.x); acc.y = fmaf(s.z, v2.y, acc.y);
                acc.z = fmaf(s.z, v2.z, acc.z); acc.w = fmaf(s.z, v2.w, acc.w);
                acc.x = fmaf(s.w, v3.x, acc.x); acc.y = fmaf(s.w, v3.y, acc.y);
                acc.z = fmaf(s.w, v3.z, acc.z); acc.w = fmaf(s.w, v3.w, acc.w);
            }
            __syncthreads();
        }

        float m = Mj[i0 + ty4];
        acc.x *= m; acc.y *= m; acc.z *= m; acc.w *= m;
        reinterpret_cast<float4*>(out)[(size_t)(b*NN + i0 + ty4)*16 + tx4] = acc;
    }
    __syncthreads();   // smem reused by next tile / copy mailbox
}

// ---------------------------------------------------------------------------
// Single-wave megakernel:
//  blocks [0,128):   qkv(32 rows) -> release -> spin for all qkv -> 2 attn
//                    tiles -> join copy
//  blocks [128,444): steal copy chunks from t=0
// ---------------------------------------------------------------------------
__global__ __launch_bounds__(256, 3) void mega_kernel(
    const float* __restrict__ x, const int* __restrict__ mask,
    const float* __restrict__ Wq, const float* __restrict__ bq,
    const float* __restrict__ Wk, const float* __restrict__ bk,
    const float* __restrict__ Wv, const float* __restrict__ bv,
    float* __restrict__ out, const float* __restrict__ e)
{
    extern __shared__ float sm[];
    const int t = threadIdx.x;

    if (blockIdx.x < QKV_BLOCKS) {
        // ---------------- qkv phase ----------------
        {
            float* xs = sm;                       // 8192 floats
            const int row0 = blockIdx.x * 32;

            const float4* x4 = reinterpret_cast<const float4*>(x + (size_t)row0 * DD);
            float4* xs4 = reinterpret_cast<float4*>(xs);
            #pragma unroll
            for (int i = t; i < 32*DD/4; i += 256) xs4[i] = x4[i];
            __syncthreads();

            const int tx = t & 63;
            const int ty = t >> 6;

            float accq[8], acck[8], accv[8];
            #pragma unroll
            for (int r = 0; r < 8; r++) { accq[r] = 0.f; acck[r] = 0.f; accv[r] = 0.f; }

            for (int k = 0; k < DD; k += 4) {
                float4 xv4[8];
                #pragma unroll
                for (int r = 0; r < 8; r++)
                    xv4[r] = *reinterpret_cast<const float4*>(&xs[(ty + r*4)*DD + k]);
                #pragma unroll
                for (int kk = 0; kk < 4; kk++) {
                    float wq = Wq[(k+kk)*DH + tx];
                    float wk = Wk[(k+kk)*DH + tx];
                    float wv = Wv[(k+kk)*DH + tx];
                    #pragma unroll
                    for (int r = 0; r < 8; r++) {
                        float xv = reinterpret_cast<const float*>(&xv4[r])[kk];
                        accq[r] = fmaf(xv, wq, accq[r]);
                        acck[r] = fmaf(xv, wk, acck[r]);
                        accv[r] = fmaf(xv, wv, accv[r]);
                    }
                }
            }

            const float bqv = bq[tx], bkv = bk[tx], bvv = bv[tx];
            #pragma unroll
            for (int r = 0; r < 8; r++) {
                int row = row0 + ty + r*4;
                float m = (float)mask[row];
                g_Q[row*DH + tx] = (accq[r] + bqv) * m;
                g_K[row*DH + tx] = (acck[r] + bkv) * m;
                g_V[row*DH + tx] = (accv[r] + bvv) * m;
            }
        }

        // release + wait for all qkv blocks (all are resident in wave 1)
        __threadfence();
        __syncthreads();
        if (t == 0) {
            atomicAdd(&g_done, 1);
            volatile int* vd = &g_done;
            while (*vd < QKV_BLOCKS) { }
        }
        __syncthreads();
        __threadfence();
        __syncthreads();

        // ---------------- attention phase: 2 tiles ----------------
        attention_tile(sm, 2*blockIdx.x,     mask, out);
        attention_tile(sm, 2*blockIdx.x + 1, mask, out);
    }

    // ---------------- copy phase: every warp steals 32KB chunks ----------------
    {
        const int lane = t & 31;
        const float4* __restrict__ src = reinterpret_cast<const float4*>(e);
        float4* __restrict__ dst = reinterpret_cast<float4*>(out + (size_t)NROWS*DH);

        for (;;) {
            int c = 0;
            if (lane == 0) c = atomicAdd(&g_chunk, 1);
            c = __shfl_sync(0xffffffffu, c, 0);
            if (c >= NCHUNKS) break;

            const size_t base = (size_t)c * CHUNK4 + lane;
            #pragma unroll 1
            for (int u = 0; u < 64; u += 8) {
                float4 r[8];
                #pragma unroll
                for (int v = 0; v < 8; v++)
                    r[v] = __ldcs(&src[base + (size_t)(u+v)*32]);
                #pragma unroll
                for (int v = 0; v < 8; v++)
                    __stcs(&dst[base + (size_t)(u+v)*32], r[v]);
            }
        }
    }

    // ---------------- replay-safe reset by last-exiting block ----------------
    __syncthreads();
    if (t == 0) {
        int ex = atomicAdd(&g_exit, 1);
        if (ex == GRID_TOTAL - 1) {
            g_chunk = 0;
            g_done  = 0;
            g_exit  = 0;
            __threadfence();
        }
    }
}

// ---------------------------------------------------------------------------
extern "C" void kernel_launch(void* const* d_in, const int* in_sizes, int n_in,
                              void* d_out, int out_size)
{
    const float* x  = (const float*)d_in[0];
    const float* e  = (const float*)d_in[1];
    const int*  msk = (const int*)  d_in[2];
    const float* Wq = (const float*)d_in[3];
    const float* bq = (const float*)d_in[4];
    const float* Wk = (const float*)d_in[5];
    const float* bk = (const float*)d_in[6];
    const float* Wv = (const float*)d_in[7];
    const float* bv = (const float*)d_in[8];
    float* out = (float*)d_out;

    cudaFuncSetAttribute(mega_kernel, cudaFuncAttributeMaxDynamicSharedMemorySize,
                         SMEM_BYTES);
    mega_kernel<<<GRID_TOTAL, 256, SMEM_BYTES>>>(
        x, msk, Wq, bq, Wk, bk, Wv, bv, out, e);
}

// round 10
// speedup vs baseline: 1.4234x; 1.4234x over previous
#include <cuda_runtime.h>

#define NB 8
#define NN 512
#define DD 256
#define DH 64
#define NROWS (NB*NN)   // 4096

#define QKV_BLOCKS 256           // 16 rows per block
#define ATTN_BLOCKS 256          // 16 q-rows per block
#define GRID_TOTAL 444           // 3 CTAs/SM * 148 SMs

// e passthrough: 16777216 float4 total; 32KB chunks stolen per-warp
#define CHUNK4    2048
#define NCHUNKS   8192

// fused kernel smem: Qs 1024 + KsT 8192 + S 8192 + Mj 512 = 17920 floats
#define SMEM_BYTES (17920 * 4)

__device__ float g_Q[NROWS*DH];
__device__ float g_K[NROWS*DH];
__device__ float g_V[NROWS*DH];
__device__ int   g_chunk;        // copy work-stealing counter (persists across kernels)
__device__ int   g_done;         // qkv completion counter
__device__ int   g_exit;         // exit counter (replay-safe reset)

// ---------------------------------------------------------------------------
// Kernel 1: blocks [0,256) project 16 rows each of Q/K/V; blocks [256,444)
// work-steal copy chunks until qkv is done (then exit, leaving the rest of
// the copy to kernel 2).
// ---------------------------------------------------------------------------
__global__ __launch_bounds__(256) void qkv_copy_kernel(
    const float* __restrict__ x, const int* __restrict__ mask,
    const float* __restrict__ Wq, const float* __restrict__ bq,
    const float* __restrict__ Wk, const float* __restrict__ bk,
    const float* __restrict__ Wv, const float* __restrict__ bv,
    float* __restrict__ out, const float* __restrict__ e)
{
    const int t = threadIdx.x;

    if (blockIdx.x < QKV_BLOCKS) {
        __shared__ float xs[16*DD];              // 16 KB
        const int row0 = blockIdx.x * 16;

        const float4* x4 = reinterpret_cast<const float4*>(x + (size_t)row0 * DD);
        float4* xs4 = reinterpret_cast<float4*>(xs);
        #pragma unroll
        for (int i = t; i < 16*DD/4; i += 256) xs4[i] = x4[i];
        __syncthreads();

        const int tx = t & 63;       // output column
        const int ty = t >> 6;       // 0..3, rows ty + 4r

        float accq[4], acck[4], accv[4];
        #pragma unroll
        for (int r = 0; r < 4; r++) { accq[r] = 0.f; acck[r] = 0.f; accv[r] = 0.f; }

        for (int k = 0; k < DD; k += 4) {
            float4 xv4[4];
            #pragma unroll
            for (int r = 0; r < 4; r++)
                xv4[r] = *reinterpret_cast<const float4*>(&xs[(ty + r*4)*DD + k]);
            #pragma unroll
            for (int kk = 0; kk < 4; kk++) {
                float wq = Wq[(k+kk)*DH + tx];
                float wk = Wk[(k+kk)*DH + tx];
                float wv = Wv[(k+kk)*DH + tx];
                #pragma unroll
                for (int r = 0; r < 4; r++) {
                    float xv = reinterpret_cast<const float*>(&xv4[r])[kk];
                    accq[r] = fmaf(xv, wq, accq[r]);
                    acck[r] = fmaf(xv, wk, acck[r]);
                    accv[r] = fmaf(xv, wv, accv[r]);
                }
            }
        }

        const float bqv = bq[tx], bkv = bk[tx], bvv = bv[tx];
        #pragma unroll
        for (int r = 0; r < 4; r++) {
            int row = row0 + ty + r*4;
            float m = (float)mask[row];
            g_Q[row*DH + tx] = (accq[r] + bqv) * m;
            g_K[row*DH + tx] = (acck[r] + bkv) * m;
            g_V[row*DH + tx] = (accv[r] + bvv) * m;
        }

        __threadfence();
        __syncthreads();
        if (t == 0) atomicAdd(&g_done, 1);
        return;
    }

    // ---- copy blocks: steal chunks until qkv done (or chunks exhausted) ----
    {
        const int lane = t & 31;
        const float4* __restrict__ src = reinterpret_cast<const float4*>(e);
        float4* __restrict__ dst = reinterpret_cast<float4*>(out + (size_t)NROWS*DH);
        volatile int* vd = &g_done;

        for (;;) {
            if (*vd >= QKV_BLOCKS) break;        // qkv finished: let kernel 2 continue

            int c = 0;
            if (lane == 0) c = atomicAdd(&g_chunk, 1);
            c = __shfl_sync(0xffffffffu, c, 0);
            if (c >= NCHUNKS) break;

            const size_t base = (size_t)c * CHUNK4 + lane;
            #pragma unroll 1
            for (int u = 0; u < 64; u += 8) {
                float4 r[8];
                #pragma unroll
                for (int v = 0; v < 8; v++)
                    r[v] = __ldcs(&src[base + (size_t)(u+v)*32]);
                #pragma unroll
                for (int v = 0; v < 8; v++)
                    __stcs(&dst[base + (size_t)(u+v)*32], r[v]);
            }
        }
    }
}

// ---------------------------------------------------------------------------
// Kernel 2 (R7 fused, proven): blocks [0,256) run one attention tile, then
// ALL warps work-steal the remaining copy chunks. Last block out resets the
// global counters so graph replays are deterministic.
// ---------------------------------------------------------------------------
__global__ __launch_bounds__(256) void fused_kernel(
    const int* __restrict__ mask, float* __restrict__ out,
    const float* __restrict__ e)
{
    extern __shared__ float sm[];
    const int t = threadIdx.x;

    if (blockIdx.x < ATTN_BLOCKS) {
        float* Qs  = sm;                  // 1024
        float* KsT = sm + 1024;           // 8192 (K: 64k x 128j / V: 128j x 64d)
        float* S   = sm + 9216;           // 8192
        float* Mj  = sm + 17408;          // 512

        const int b  = blockIdx.x >> 5;
        const int i0 = (blockIdx.x & 31) * 16;

        for (int j = t; j < NN; j += 256) Mj[j] = (float)mask[b*NN + j];
        {
            const float4* q4 = reinterpret_cast<const float4*>(g_Q + (size_t)(b*NN + i0)*DH);
            reinterpret_cast<float4*>(Qs)[t] = q4[t];
        }
        __syncthreads();

        const int tx = t & 31;
        const int ty = t >> 5;
        float4* Qs4  = reinterpret_cast<float4*>(Qs);
        float4* KsT4 = reinterpret_cast<float4*>(KsT);
        float4* S4   = reinterpret_cast<float4*>(S);

        for (int jt = 0; jt < 4; jt++) {
            const int j0 = jt * 128;
            {
                const int j    = t & 127;
                const int half = t >> 7;
                const float4* K4 = reinterpret_cast<const float4*>(g_K) +
                                   (size_t)(b*NN + j0 + j) * 16;
                #pragma unroll
                for (int i2 = 0; i2 < 8; i2++) {
                    int k4 = half*8 + i2;
                    float4 v = K4[k4];
                    KsT[(k4*4+0)*128 + j] = v.x;
                    KsT[(k4*4+1)*128 + j] = v.y;
                    KsT[(k4*4+2)*128 + j] = v.z;
                    KsT[(k4*4+3)*128 + j] = v.w;
                }
            }
            __syncthreads();

            float acc[2][4];
            #pragma unroll
            for (int c = 0; c < 2; c++)
                #pragma unroll
                for (int a = 0; a < 4; a++) acc[c][a] = 0.f;

            #pragma unroll 4
            for (int k4 = 0; k4 < 16; k4++) {
                float4 q0 = Qs4[ ty    *16 + k4];
                float4 q1 = Qs4[(ty+8)*16 + k4];
                #pragma unroll
                for (int kk = 0; kk < 4; kk++) {
                    float4 kv = KsT4[(k4*4 + kk)*32 + tx];
                    float qa = reinterpret_cast<const float*>(&q0)[kk];
                    float qb = reinterpret_cast<const float*>(&q1)[kk];
                    acc[0][0] = fmaf(qa, kv.x, acc[0][0]);
                    acc[0][1] = fmaf(qa, kv.y, acc[0][1]);
                    acc[0][2] = fmaf(qa, kv.z, acc[0][2]);
                    acc[0][3] = fmaf(qa, kv.w, acc[0][3]);
                    acc[1][0] = fmaf(qb, kv.x, acc[1][0]);
                    acc[1][1] = fmaf(qb, kv.y, acc[1][1]);
                    acc[1][2] = fmaf(qb, kv.z, acc[1][2]);
                    acc[1][3] = fmaf(qb, kv.w, acc[1][3]);
                }
            }

            {
                const float mi0 = Mj[i0 + ty];
                const float mi1 = Mj[i0 + ty + 8];
                const int jb = j0 + tx*4;
                float4 s0, s1;
                s0.x = (mi0*Mj[jb+0] != 0.f) ? acc[0][0]*0.125f : -1.0e9f;
                s0.y = (mi0*Mj[jb+1] != 0.f) ? acc[0][1]*0.125f : -1.0e9f;
                s0.z = (mi0*Mj[jb+2] != 0.f) ? acc[0][2]*0.125f : -1.0e9f;
                s0.w = (mi0*Mj[jb+3] != 0.f) ? acc[0][3]*0.125f : -1.0e9f;
                s1.x = (mi1*Mj[jb+0] != 0.f) ? acc[1][0]*0.125f : -1.0e9f;
                s1.y = (mi1*Mj[jb+1] != 0.f) ? acc[1][1]*0.125f : -1.0e9f;
                s1.z = (mi1*Mj[jb+2] != 0.f) ? acc[1][2]*0.125f : -1.0e9f;
                s1.w = (mi1*Mj[jb+3] != 0.f) ? acc[1][3]*0.125f : -1.0e9f;
                S4[ ty    *128 + (jb>>2)] = s0;
                S4[(ty+8)*128 + (jb>>2)] = s1;
            }
            __syncthreads();
        }

        // softmax: warp per row pair
        {
            const int warp = t >> 5, lane = t & 31;
            #pragma unroll
            for (int rr = 0; rr < 2; rr++) {
                int row = warp*2 + rr;
                float vals[16];
                float mx = -3.4e38f;
                #pragma unroll
                for (int m = 0; m < 16; m++) {
                    vals[m] = S[row*NN + lane + 32*m];
                    mx = fmaxf(mx, vals[m]);
                }
                #pragma unroll
                for (int o = 16; o > 0; o >>= 1)
                    mx = fmaxf(mx, __shfl_xor_sync(0xffffffffu, mx, o));
                float sum = 0.f;
                #pragma unroll
                for (int m = 0; m < 16; m++) { vals[m] = __expf(vals[m] - mx); sum += vals[m]; }
                #pragma unroll
                for (int o = 16; o > 0; o >>= 1)
                    sum += __shfl_xor_sync(0xffffffffu, sum, o);
                float inv = 1.f / sum;
                #pragma unroll
                for (int m = 0; m < 16; m++) S[row*NN + lane + 32*m] = vals[m]*inv;
            }
        }
        __syncthreads();

        // out = P @ V, V staged through smem in 4 j-tiles
        {
            const int ty4 = t >> 4;
            const int tx4 = t & 15;
            float4 acc = {0.f, 0.f, 0.f, 0.f};
            float4* Vs4 = reinterpret_cast<float4*>(KsT);
            const float4* __restrict__ V4 =
                reinterpret_cast<const float4*>(g_V) + (size_t)b*NN*16;

            for (int jt = 0; jt < 4; jt++) {
                const int j0 = jt * 128;
                #pragma unroll
                for (int i2 = 0; i2 < 8; i2++) {
                    int idx = t + i2*256;
                    int row = idx >> 4, c4 = idx & 15;
                    Vs4[row*16 + c4] = V4[(size_t)(j0 + row)*16 + c4];
                }
                __syncthreads();

                #pragma unroll 4
                for (int j4 = 0; j4 < 32; j4++) {
                    float4 s  = S4[ty4*128 + jt*32 + j4];
                    float4 v0 = Vs4[(j4*4+0)*16 + tx4];
                    float4 v1 = Vs4[(j4*4+1)*16 + tx4];
                    float4 v2 = Vs4[(j4*4+2)*16 + tx4];
                    float4 v3 = Vs4[(j4*4+3)*16 + tx4];
                    acc.x = fmaf(s.x, v0.x, acc.x); acc.y = fmaf(s.x, v0.y, acc.y);
                    acc.z = fmaf(s.x, v0.z, acc.z); acc.w = fmaf(s.x, v0.w, acc.w);
                    acc.x = fmaf(s.y, v1.x, acc.x); acc.y = fmaf(s.y, v1.y, acc.y);
                    acc.z = fmaf(s.y, v1.z, acc.z); acc.w = fmaf(s.y, v1.w, acc.w);
                    acc.x = fmaf(s.z, v2.x, acc.x); acc.y = fmaf(s.z, v2.y, acc.y);
                    acc.z = fmaf(s.z, v2.z, acc.z); acc.w = fmaf(s.z, v2.w, acc.w);
                    acc.x = fmaf(s.w, v3.x, acc.x); acc.y = fmaf(s.w, v3.y, acc.y);
                    acc.z = fmaf(s.w, v3.z, acc.z); acc.w = fmaf(s.w, v3.w, acc.w);
                }
                __syncthreads();
            }

            float m = Mj[i0 + ty4];
            acc.x *= m; acc.y *= m; acc.z *= m; acc.w *= m;
            reinterpret_cast<float4*>(out)[(size_t)(b*NN + i0 + ty4)*16 + tx4] = acc;
        }
        __syncthreads();
    }

    // -------- copy phase: every warp work-steals remaining 32KB chunks --------
    {
        const int lane = t & 31;
        const float4* __restrict__ src = reinterpret_cast<const float4*>(e);
        float4* __restrict__ dst = reinterpret_cast<float4*>(out + (size_t)NROWS*DH);

        for (;;) {
            int c = 0;
            if (lane == 0) c = atomicAdd(&g_chunk, 1);
            c = __shfl_sync(0xffffffffu, c, 0);
            if (c >= NCHUNKS) break;

            const size_t base = (size_t)c * CHUNK4 + lane;
            #pragma unroll 1
            for (int u = 0; u < 64; u += 8) {
                float4 r[8];
                #pragma unroll
                for (int v = 0; v < 8; v++)
                    r[v] = __ldcs(&src[base + (size_t)(u+v)*32]);
                #pragma unroll
                for (int v = 0; v < 8; v++)
                    __stcs(&dst[base + (size_t)(u+v)*32], r[v]);
            }
        }
    }

    // -------- replay-safe reset by the last block out --------
    __syncthreads();
    if (t == 0) {
        int ex = atomicAdd(&g_exit, 1);
        if (ex == GRID_TOTAL - 1) {
            g_chunk = 0;
            g_done  = 0;
            g_exit  = 0;
            __threadfence();
        }
    }
}

// ---------------------------------------------------------------------------
extern "C" void kernel_launch(void* const* d_in, const int* in_sizes, int n_in,
                              void* d_out, int out_size)
{
    const float* x  = (const float*)d_in[0];
    const float* e  = (const float*)d_in[1];
    const int*  msk = (const int*)  d_in[2];
    const float* Wq = (const float*)d_in[3];
    const float* bq = (const float*)d_in[4];
    const float* Wk = (const float*)d_in[5];
    const float* bk = (const float*)d_in[6];
    const float* Wv = (const float*)d_in[7];
    const float* bv = (const float*)d_in[8];
    float* out = (float*)d_out;

    qkv_copy_kernel<<<GRID_TOTAL, 256>>>(x, msk, Wq, bq, Wk, bk, Wv, bv, out, e);

    cudaFuncSetAttribute(fused_kernel, cudaFuncAttributeMaxDynamicSharedMemorySize,
                         SMEM_BYTES);
    fused_kernel<<<GRID_TOTAL, 256, SMEM_BYTES>>>(msk, out, e);
}